// round 2
// baseline (speedup 1.0000x reference)
#include <cuda_runtime.h>
#include <cuda_fp16.h>

// Problem constants
#define NB 8
#define CIN 8
#define COUT 16
#define DI 64
#define DO 66
#define SP_O 287496   // 66*66*66
#define SP_I 262144   // 64*64*64

__device__ float g_sum[32], g_ssum[32], g_mean[32], g_rstd[32];

__global__ void zero_stats() {
    int t = threadIdx.x;
    g_sum[t] = 0.f;
    g_ssum[t] = 0.f;
}

__device__ __forceinline__ void ffma2(unsigned long long &d, unsigned long long a, unsigned long long b) {
    asm("fma.rn.f32x2 %0, %1, %2, %0;" : "+l"(d) : "l"(a), "l"(b));
}
__device__ __forceinline__ unsigned long long pack2(float x) {
    unsigned long long r;
    asm("mov.b64 %0, {%1, %1};" : "=l"(r) : "f"(x));
    return r;
}
__device__ __forceinline__ void unpack2(unsigned long long v, float &lo, float &hi) {
    asm("mov.b64 {%0, %1}, %2;" : "=f"(lo), "=f"(hi) : "l"(v));
}

// Block: 256 threads, computes a 4(D)x8(H)x8(W) output tile for ALL 16 output channels.
__global__ __launch_bounds__(256) void conv_kernel(const float* __restrict__ x,
                                                   const float* __restrict__ w,
                                                   float* __restrict__ out)
{
    __shared__ __align__(16) float xs[4800];   // [ci=8][d=6][h=10][w=10]
    __shared__ __align__(16) float ws[3456];   // [(ci*27+j)*16 + co]
    __shared__ float wred[64];

    const int tid = threadIdx.x;
    const int twx = blockIdx.x;          // W tile (0..8)
    const int thy = blockIdx.y % 9;      // H tile (0..8)
    const int tdz = blockIdx.y / 9;      // D tile (0..16)
    const int n   = blockIdx.z;

    // --- load weights, round to fp16 to match reference ---
    for (int s = tid; s < 3456; s += 256) {
        int co = s & 15;
        int cj = s >> 4;
        int ci = cj / 27;
        int j  = cj - ci * 27;
        float v = w[(ci * 16 + co) * 27 + j];
        ws[s] = __half2float(__float2half(v));
    }

    const int o0d = tdz * 4, o0h = thy * 8, o0w = twx * 8;

    // --- load x tile (zero-padded) ---
    const float* xn = x + (size_t)n * (CIN * SP_I);
    for (int s = tid; s < 4800; s += 256) {
        int ci = s / 600;
        int r  = s - ci * 600;
        int di = r / 100;  r -= di * 100;
        int hi = r / 10;
        int wi = r - hi * 10;
        int id = o0d - 2 + di, ih = o0h - 2 + hi, iw = o0w - 2 + wi;
        float v = 0.f;
        if ((unsigned)id < 64u && (unsigned)ih < 64u && (unsigned)iw < 64u)
            v = xn[ci * SP_I + id * 4096 + ih * 64 + iw];
        xs[s] = v;
    }
    __syncthreads();

    const int dx = tid & 7, dy = (tid >> 3) & 7, dz = tid >> 6;

    unsigned long long acc[8];
    #pragma unroll
    for (int p = 0; p < 8; ++p) acc[p] = 0ull;

    // y[o] = sum_{ci,j} x[o - j] * w16[ci,co,j]
    #pragma unroll 1
    for (int ci = 0; ci < CIN; ++ci) {
        const float* xb = xs + ci * 600 + (dz + 2) * 100 + (dy + 2) * 10 + (dx + 2);
        const unsigned long long* wb = (const unsigned long long*)(ws + ci * 27 * 16);
        #pragma unroll
        for (int j = 0; j < 27; ++j) {
            const int jd = j / 9, jh = (j / 3) % 3, jw = j % 3;
            float xv = xb[-(jd * 100 + jh * 10 + jw)];
            unsigned long long xx = pack2(xv);
            #pragma unroll
            for (int p = 0; p < 8; ++p) ffma2(acc[p], xx, wb[j * 8 + p]);
        }
    }

    // --- ReLU + store + per-group partial stats ---
    const int od = o0d + dz, oh = o0h + dy, ow = o0w + dx;
    const bool inb = (od < 66) && (oh < 66) && (ow < 66);
    float s4[4] = {0.f, 0.f, 0.f, 0.f};
    float q4[4] = {0.f, 0.f, 0.f, 0.f};
    float* on = out + (size_t)n * (COUT * SP_O) + od * 4356 + oh * 66 + ow;
    #pragma unroll
    for (int p = 0; p < 8; ++p) {
        float v0, v1;
        unpack2(acc[p], v0, v1);
        v0 = fmaxf(v0, 0.f);
        v1 = fmaxf(v1, 0.f);
        if (inb) {
            on[(size_t)(2 * p) * SP_O]     = v0;
            on[(size_t)(2 * p + 1) * SP_O] = v1;
            int g = p >> 1;
            s4[g] += v0 + v1;
            q4[g] += v0 * v0 + v1 * v1;
        }
    }

    // warp reduce, then cross-warp via smem, then 8 atomics/block
    #pragma unroll
    for (int g = 0; g < 4; ++g) {
        #pragma unroll
        for (int o = 16; o > 0; o >>= 1) {
            s4[g] += __shfl_down_sync(0xffffffffu, s4[g], o);
            q4[g] += __shfl_down_sync(0xffffffffu, q4[g], o);
        }
    }
    const int wid = tid >> 5, lid = tid & 31;
    if (lid == 0) {
        #pragma unroll
        for (int g = 0; g < 4; ++g) {
            wred[wid * 8 + g]     = s4[g];
            wred[wid * 8 + 4 + g] = q4[g];
        }
    }
    __syncthreads();
    if (tid < 8) {
        float a = 0.f;
        #pragma unroll
        for (int wI = 0; wI < 8; ++wI) a += wred[wI * 8 + tid];
        if (tid < 4) atomicAdd(&g_sum[n * 4 + tid], a);
        else         atomicAdd(&g_ssum[n * 4 + (tid - 4)], a);
    }
}

__global__ void finalize_stats() {
    int t = threadIdx.x;  // 0..31 == n*4+g
    const float inv_cnt = 1.0f / (4.0f * (float)SP_O);
    float m = g_sum[t] * inv_cnt;
    float v = g_ssum[t] * inv_cnt - m * m;
    g_mean[t] = m;
    g_rstd[t] = rsqrtf(v + 1e-5f);
}

__global__ __launch_bounds__(256) void norm_kernel(float* __restrict__ out,
                                                   const float* __restrict__ gamma,
                                                   const float* __restrict__ beta)
{
    int idx = blockIdx.x * 256 + threadIdx.x;   // float4 index
    int e = idx * 4;
    int c_all = e / SP_O;          // n*16 + c   (0..127)
    int n = c_all >> 4;
    int c = c_all & 15;
    int g = c >> 2;
    float m = g_mean[n * 4 + g];
    float r = g_rstd[n * 4 + g];
    float a = r * gamma[c];
    float b = beta[c] - m * a;
    float4 v = ((const float4*)out)[idx];
    v.x = v.x * a + b;
    v.y = v.y * a + b;
    v.z = v.z * a + b;
    v.w = v.w * a + b;
    ((float4*)out)[idx] = v;
}

extern "C" void kernel_launch(void* const* d_in, const int* in_sizes, int n_in,
                              void* d_out, int out_size) {
    const float* x     = (const float*)d_in[0];
    const float* w     = (const float*)d_in[1];
    const float* gamma = (const float*)d_in[2];
    const float* beta  = (const float*)d_in[3];
    float* out = (float*)d_out;

    zero_stats<<<1, 32>>>();
    dim3 grid(9, 9 * 17, 8);           // W tiles, H*D tiles, batch
    conv_kernel<<<grid, 256>>>(x, w, out);
    finalize_stats<<<1, 32>>>();
    norm_kernel<<<35937, 256>>>(out, gamma, beta);   // 36799488/4/256
}

// round 5
// speedup vs baseline: 1.8076x; 1.8076x over previous
#include <cuda_runtime.h>
#include <cuda_fp16.h>

#define SP_O 287496   // 66^3
#define SP_I 262144   // 64^3

__device__ float g_sum[32], g_ssum[32], g_mean[32], g_rstd[32];
__device__ __align__(16) float g_w16[3456];   // [(ci*27 + j)*16 + co], fp16-rounded

__global__ void zero_stats() {
    int t = threadIdx.x;
    g_sum[t] = 0.f;
    g_ssum[t] = 0.f;
}

__global__ void prep_weights(const float* __restrict__ w) {
    int idx = blockIdx.x * 256 + threadIdx.x;
    if (idx < 3456) {
        int co = idx & 15;
        int cj = idx >> 4;          // ci*27 + j
        int ci = cj / 27;
        int j  = cj - ci * 27;
        g_w16[idx] = __half2float(__float2half(w[(ci * 16 + co) * 27 + j]));
    }
}

__device__ __forceinline__ void ffma2(unsigned long long &d, unsigned long long a, unsigned long long b) {
    asm("fma.rn.f32x2 %0, %1, %2, %0;" : "+l"(d) : "l"(a), "l"(b));
}
__device__ __forceinline__ unsigned long long pack2(float x) {
    unsigned long long r;
    asm("mov.b64 %0, {%1, %1};" : "=l"(r) : "f"(x));
    return r;
}
__device__ __forceinline__ void unpack2(unsigned long long v, float &lo, float &hi) {
    asm("mov.b64 {%0, %1}, %2;" : "=f"(lo), "=f"(hi) : "l"(v));
}

// Block: 256 threads (242 active as 11x11x2), tile = 11(W) x 11(H) x 6(D), all 16 co.
// Each active thread: 3 consecutive D outputs x 16 co, accumulated in packed f32x2.
__global__ __launch_bounds__(256, 2) void conv_kernel(const float* __restrict__ x,
                                                      float* __restrict__ out)
{
    __shared__ __align__(16) float xs[4 * 1352];  // [ci4][d=8][h=13 * w=13]
    __shared__ __align__(16) float ws[3456];
    __shared__ float wred[64];

    const int tid = threadIdx.x;
    const bool active = tid < 242;
    const int dx = tid % 11;
    const int dy = (tid / 11) % 11;
    const int dz = tid / 121;          // 0..1 (garbage for inactive, unused)

    const int w0 = blockIdx.x * 11;
    const int h0 = blockIdx.y * 11;
    const int bz = blockIdx.z;         // 0..87
    const int n  = bz / 11;
    const int d0 = (bz - n * 11) * 6;

    // weights (already fp16-rounded) into smem
    {
        const float4* src = (const float4*)g_w16;
        for (int s = tid; s < 864; s += 256) ((float4*)ws)[s] = src[s];
    }

    unsigned long long acc[3][8];
    #pragma unroll
    for (int k = 0; k < 3; ++k)
        #pragma unroll
        for (int p = 0; p < 8; ++p) acc[k][p] = 0ull;

    const float* xn = x + (size_t)n * (8 * SP_I);

    #pragma unroll 1
    for (int half = 0; half < 2; ++half) {
        __syncthreads();
        // stage 4 input channels: window d[8] x h[13] x w[13], zero-padded
        const float* xh = xn + half * 4 * SP_I;
        for (int s = tid; s < 5408; s += 256) {
            int ci = s / 1352;
            int r  = s - ci * 1352;
            int dl = r / 169;  r -= dl * 169;
            int hl = r / 13;
            int wl = r - hl * 13;
            int id = d0 - 2 + dl, ih = h0 - 2 + hl, iw = w0 - 2 + wl;
            float v = 0.f;
            if ((unsigned)id < 64u && (unsigned)ih < 64u && (unsigned)iw < 64u)
                v = xh[ci * SP_I + (id * 64 + ih) * 64 + iw];
            xs[s] = v;
        }
        __syncthreads();

        if (active) {
            #pragma unroll 1
            for (int ci4 = 0; ci4 < 4; ++ci4) {
                const int ci = half * 4 + ci4;
                const float* xbase = xs + ci4 * 1352 + (dz * 3 + 2) * 169 + (dy + 2) * 13 + (dx + 2);
                const unsigned long long* wsp = (const unsigned long long*)ws;
                #pragma unroll
                for (int jh = 0; jh < 3; ++jh) {
                    #pragma unroll
                    for (int jw = 0; jw < 3; ++jw) {
                        const float* xp = xbase - jh * 13 - jw;
                        unsigned long long xx[5];
                        #pragma unroll
                        for (int t = 0; t < 5; ++t) xx[t] = pack2(xp[(t - 2) * 169]);
                        const unsigned long long* wb = wsp + (ci * 27 + jh * 3 + jw) * 8;
                        #pragma unroll
                        for (int jd = 0; jd < 3; ++jd) {
                            unsigned long long wr[8];
                            #pragma unroll
                            for (int p = 0; p < 8; ++p) wr[p] = wb[jd * 72 + p];
                            #pragma unroll
                            for (int k = 0; k < 3; ++k)
                                #pragma unroll
                                for (int p = 0; p < 8; ++p)
                                    ffma2(acc[k][p], xx[k - jd + 2], wr[p]);
                        }
                    }
                }
            }
        }
    }

    // epilogue: ReLU + store + per-group stats (exact tiling: no bounds checks)
    float s4[4] = {0.f, 0.f, 0.f, 0.f};
    float q4[4] = {0.f, 0.f, 0.f, 0.f};
    if (active) {
        const int od0 = d0 + dz * 3;
        float* on = out + (size_t)n * (16 * SP_O) + (od0 * 66 + (h0 + dy)) * 66 + (w0 + dx);
        #pragma unroll
        for (int k = 0; k < 3; ++k) {
            float* ok = on + k * 4356;
            #pragma unroll
            for (int p = 0; p < 8; ++p) {
                float v0, v1;
                unpack2(acc[k][p], v0, v1);
                v0 = fmaxf(v0, 0.f);
                v1 = fmaxf(v1, 0.f);
                ok[(size_t)(2 * p) * SP_O]     = v0;
                ok[(size_t)(2 * p + 1) * SP_O] = v1;
                int g = p >> 1;
                s4[g] += v0 + v1;
                q4[g] += v0 * v0 + v1 * v1;
            }
        }
    }

    #pragma unroll
    for (int g = 0; g < 4; ++g) {
        #pragma unroll
        for (int o = 16; o > 0; o >>= 1) {
            s4[g] += __shfl_down_sync(0xffffffffu, s4[g], o);
            q4[g] += __shfl_down_sync(0xffffffffu, q4[g], o);
        }
    }
    const int wid = tid >> 5, lid = tid & 31;
    if (lid == 0) {
        #pragma unroll
        for (int g = 0; g < 4; ++g) {
            wred[wid * 8 + g]     = s4[g];
            wred[wid * 8 + 4 + g] = q4[g];
        }
    }
    __syncthreads();
    if (tid < 8) {
        float a = 0.f;
        #pragma unroll
        for (int wI = 0; wI < 8; ++wI) a += wred[wI * 8 + tid];
        if (tid < 4) atomicAdd(&g_sum[n * 4 + tid], a);
        else         atomicAdd(&g_ssum[n * 4 + (tid - 4)], a);
    }
}

__global__ void finalize_stats() {
    int t = threadIdx.x;  // n*4+g
    const float inv_cnt = 1.0f / (4.0f * (float)SP_O);
    float m = g_sum[t] * inv_cnt;
    float v = g_ssum[t] * inv_cnt - m * m;
    g_mean[t] = m;
    g_rstd[t] = rsqrtf(v + 1e-5f);
}

__global__ __launch_bounds__(256) void norm_kernel(float* __restrict__ out,
                                                   const float* __restrict__ gamma,
                                                   const float* __restrict__ beta)
{
    int idx = blockIdx.x * 256 + threadIdx.x;   // float4 index
    int e = idx * 4;
    int c_all = e / SP_O;          // n*16 + c
    int n = c_all >> 4;
    int c = c_all & 15;
    int g = c >> 2;
    float m = g_mean[n * 4 + g];
    float r = g_rstd[n * 4 + g];
    float a = r * gamma[c];
    float b = beta[c] - m * a;
    float4 v = ((const float4*)out)[idx];
    v.x = v.x * a + b;
    v.y = v.y * a + b;
    v.z = v.z * a + b;
    v.w = v.w * a + b;
    ((float4*)out)[idx] = v;
}

extern "C" void kernel_launch(void* const* d_in, const int* in_sizes, int n_in,
                              void* d_out, int out_size) {
    const float* x     = (const float*)d_in[0];
    const float* w     = (const float*)d_in[1];
    const float* gamma = (const float*)d_in[2];
    const float* beta  = (const float*)d_in[3];
    float* out = (float*)d_out;

    zero_stats<<<1, 32>>>();
    prep_weights<<<14, 256>>>(w);
    dim3 grid(6, 6, 88);                 // W tiles, H tiles, D tiles * batch
    conv_kernel<<<grid, 256>>>(x, out);
    finalize_stats<<<1, 32>>>();
    norm_kernel<<<35937, 256>>>(out, gamma, beta);
}

// round 6
// speedup vs baseline: 1.8734x; 1.0364x over previous
#include <cuda_runtime.h>
#include <cuda_fp16.h>

#define SP_O 287496   // 66^3
#define SP_I 262144   // 64^3

__device__ float g_sum[32], g_ssum[32], g_mean[32], g_rstd[32];
__device__ __align__(16) float g_w16[3456];   // [(ci*27 + j)*16 + co], fp16-rounded

__global__ void prep_weights(const float* __restrict__ w) {
    int idx = blockIdx.x * 256 + threadIdx.x;
    if (idx < 32) {               // fold zero_stats here
        g_sum[idx] = 0.f;
        g_ssum[idx] = 0.f;
    }
    if (idx < 3456) {
        int co = idx & 15;
        int cj = idx >> 4;          // ci*27 + j
        int ci = cj / 27;
        int j  = cj - ci * 27;
        g_w16[idx] = __half2float(__float2half(w[(ci * 16 + co) * 27 + j]));
    }
}

__device__ __forceinline__ void ffma2(unsigned long long &d, unsigned long long a, unsigned long long b) {
    asm("fma.rn.f32x2 %0, %1, %2, %0;" : "+l"(d) : "l"(a), "l"(b));
}
__device__ __forceinline__ unsigned long long pack2(float x) {
    unsigned long long r;
    asm("mov.b64 %0, {%1, %1};" : "=l"(r) : "f"(x));
    return r;
}
__device__ __forceinline__ void unpack2(unsigned long long v, float &lo, float &hi) {
    asm("mov.b64 {%0, %1}, %2;" : "=f"(lo), "=f"(hi) : "l"(v));
}

// Block: 128 threads (121 active as 11x11), tile = 11(W) x 11(H) x 6(D), all 16 co.
// Each active thread: 6 consecutive D outputs x 16 co in packed f32x2 accumulators.
// Weights read via __ldg (L1), x via one smem stage of all 8 ci.
__global__ __launch_bounds__(128, 3) void conv_kernel(const float* __restrict__ x,
                                                      float* __restrict__ out)
{
    __shared__ __align__(16) float xs[8 * 1352];  // [ci=8][d=8][h=13][w=13]
    __shared__ float wred[32];

    const int tid = threadIdx.x;
    const bool active = tid < 121;

    const int w0 = blockIdx.x * 11;
    const int h0 = blockIdx.y * 11;
    const int bz = blockIdx.z;           // 0..87
    const int n  = bz / 11;
    const int d0 = (bz - n * 11) * 6;

    // --- stage x tile: all 8 ci, window d[8] x h[13] x w[13], zero-padded ---
    const float* xn = x + (size_t)n * (8 * SP_I);
    for (int s = tid; s < 10816; s += 128) {
        int ci = s / 1352;
        int r  = s - ci * 1352;
        int dl = r / 169;  r -= dl * 169;
        int hl = r / 13;
        int wl = r - hl * 13;
        int id = d0 - 2 + dl, ih = h0 - 2 + hl, iw = w0 - 2 + wl;
        float v = 0.f;
        if ((unsigned)id < 64u && (unsigned)ih < 64u && (unsigned)iw < 64u)
            v = xn[ci * SP_I + (id * 64 + ih) * 64 + iw];
        xs[s] = v;
    }
    __syncthreads();

    const int dx = active ? (tid % 11) : 0;
    const int dy = active ? (tid / 11) : 0;

    unsigned long long acc[6][8];
    #pragma unroll
    for (int k = 0; k < 6; ++k)
        #pragma unroll
        for (int p = 0; p < 8; ++p) acc[k][p] = 0ull;

    if (active) {
        const unsigned long long* gw = (const unsigned long long*)g_w16;
        #pragma unroll 1
        for (int ci = 0; ci < 8; ++ci) {
            const float* xb = xs + ci * 1352 + 2 * 169 + (dy + 2) * 13 + (dx + 2);
            const unsigned long long* wci = gw + ci * 27 * 8;
            #pragma unroll
            for (int jh = 0; jh < 3; ++jh) {
                #pragma unroll
                for (int jw = 0; jw < 3; ++jw) {
                    const float* xp = xb - jh * 13 - jw;
                    unsigned long long xx[8];
                    #pragma unroll
                    for (int t = 0; t < 8; ++t) xx[t] = pack2(xp[(t - 2) * 169]);
                    #pragma unroll
                    for (int jd = 0; jd < 3; ++jd) {
                        const unsigned long long* wb = wci + (jd * 9 + jh * 3 + jw) * 8;
                        unsigned long long wr[8];
                        #pragma unroll
                        for (int p = 0; p < 8; ++p) wr[p] = __ldg(wb + p);
                        #pragma unroll
                        for (int k = 0; k < 6; ++k)
                            #pragma unroll
                            for (int p = 0; p < 8; ++p)
                                ffma2(acc[k][p], xx[k + 2 - jd], wr[p]);
                    }
                }
            }
        }
    }

    // --- epilogue: ReLU + store + per-group stats (exact tiling) ---
    float s4[4] = {0.f, 0.f, 0.f, 0.f};
    float q4[4] = {0.f, 0.f, 0.f, 0.f};
    if (active) {
        float* on = out + (size_t)n * (16 * SP_O) + (d0 * 66 + (h0 + dy)) * 66 + (w0 + dx);
        #pragma unroll
        for (int k = 0; k < 6; ++k) {
            float* ok = on + k * 4356;
            #pragma unroll
            for (int p = 0; p < 8; ++p) {
                float v0, v1;
                unpack2(acc[k][p], v0, v1);
                v0 = fmaxf(v0, 0.f);
                v1 = fmaxf(v1, 0.f);
                ok[(size_t)(2 * p) * SP_O]     = v0;
                ok[(size_t)(2 * p + 1) * SP_O] = v1;
                int g = p >> 1;
                s4[g] += v0 + v1;
                q4[g] += v0 * v0 + v1 * v1;
            }
        }
    }

    #pragma unroll
    for (int g = 0; g < 4; ++g) {
        #pragma unroll
        for (int o = 16; o > 0; o >>= 1) {
            s4[g] += __shfl_down_sync(0xffffffffu, s4[g], o);
            q4[g] += __shfl_down_sync(0xffffffffu, q4[g], o);
        }
    }
    const int wid = tid >> 5, lid = tid & 31;
    if (lid == 0) {
        #pragma unroll
        for (int g = 0; g < 4; ++g) {
            wred[wid * 8 + g]     = s4[g];
            wred[wid * 8 + 4 + g] = q4[g];
        }
    }
    __syncthreads();
    if (tid < 8) {
        float a = 0.f;
        #pragma unroll
        for (int wI = 0; wI < 4; ++wI) a += wred[wI * 8 + tid];
        if (tid < 4) atomicAdd(&g_sum[n * 4 + tid], a);
        else         atomicAdd(&g_ssum[n * 4 + (tid - 4)], a);
    }
}

__global__ void finalize_stats() {
    int t = threadIdx.x;  // n*4+g
    const float inv_cnt = 1.0f / (4.0f * (float)SP_O);
    float m = g_sum[t] * inv_cnt;
    float v = g_ssum[t] * inv_cnt - m * m;
    g_mean[t] = m;
    g_rstd[t] = rsqrtf(v + 1e-5f);
}

__global__ __launch_bounds__(256) void norm_kernel(float* __restrict__ out,
                                                   const float* __restrict__ gamma,
                                                   const float* __restrict__ beta)
{
    int idx = blockIdx.x * 256 + threadIdx.x;   // float4 index
    int e = idx * 4;
    int c_all = e / SP_O;          // n*16 + c
    int n = c_all >> 4;
    int c = c_all & 15;
    int g = c >> 2;
    float m = g_mean[n * 4 + g];
    float r = g_rstd[n * 4 + g];
    float a = r * gamma[c];
    float b = beta[c] - m * a;
    float4 v = ((const float4*)out)[idx];
    v.x = v.x * a + b;
    v.y = v.y * a + b;
    v.z = v.z * a + b;
    v.w = v.w * a + b;
    ((float4*)out)[idx] = v;
}

extern "C" void kernel_launch(void* const* d_in, const int* in_sizes, int n_in,
                              void* d_out, int out_size) {
    const float* x     = (const float*)d_in[0];
    const float* w     = (const float*)d_in[1];
    const float* gamma = (const float*)d_in[2];
    const float* beta  = (const float*)d_in[3];
    float* out = (float*)d_out;

    prep_weights<<<14, 256>>>(w);
    dim3 grid(6, 6, 88);                 // W tiles, H tiles, (D tiles=11) * batch
    conv_kernel<<<grid, 128>>>(x, out);
    finalize_stats<<<1, 32>>>();
    norm_kernel<<<35937, 256>>>(out, gamma, beta);
}

// round 9
// speedup vs baseline: 4.2692x; 2.2789x over previous
#include <cuda_runtime.h>
#include <cuda_fp16.h>
#include <cstdint>

#define SP_O 287496   // 66^3
#define SP_I 262144   // 64^3
#define PLW 68        // padded plane row stride (66 + 2 halo)
#define PL  4488      // 66*68

__device__ float g_sum[32], g_ssum[32], g_mean[32], g_rstd[32];
__device__ uint32_t g_wfrag[1728];   // [tap(27)][nh(2)][lane(32)] packed half2 B-fragments

// ---------- helpers ----------
__device__ __forceinline__ uint32_t smem_u32(const void* p) {
    uint32_t a;
    asm("{ .reg .u64 t; cvta.to.shared.u64 t, %1; cvt.u32.u64 %0, t; }" : "=r"(a) : "l"(p));
    return a;
}
__device__ __forceinline__ void ldsm4(uint32_t& a0, uint32_t& a1, uint32_t& a2, uint32_t& a3, uint32_t addr) {
    asm volatile("ldmatrix.sync.aligned.m8n8.x4.shared.b16 {%0,%1,%2,%3}, [%4];"
                 : "=r"(a0), "=r"(a1), "=r"(a2), "=r"(a3) : "r"(addr));
}
__device__ __forceinline__ void mma16816(float* c, uint32_t a0, uint32_t a1, uint32_t a2, uint32_t a3, uint32_t b) {
    asm volatile("mma.sync.aligned.m16n8k16.row.col.f32.f16.f16.f32 "
                 "{%0,%1,%2,%3},{%4,%5,%6,%7},{%8,%9},{%0,%1,%2,%3};"
                 : "+f"(c[0]), "+f"(c[1]), "+f"(c[2]), "+f"(c[3])
                 : "r"(a0), "r"(a1), "r"(a2), "r"(a3), "r"(b), "r"(b));
}
__device__ __forceinline__ uint32_t packh2(float a, float b) {
    __half2 h = __floats2half2_rn(a, b);
    return *reinterpret_cast<uint32_t*>(&h);
}

// ---------- prep: B fragments (fp16-rounded weights) + zero stats ----------
__global__ void prep_weights(const float* __restrict__ w) {
    int idx = blockIdx.x * 256 + threadIdx.x;
    if (idx < 32) { g_sum[idx] = 0.f; g_ssum[idx] = 0.f; }
    if (idx < 1728) {
        int tap = idx >> 6, r = idx & 63, nh = r >> 5, lane = r & 31;
        int ci0 = (lane & 3) * 2, co = nh * 8 + (lane >> 2);
        // b0 element pair: B[k][n], B[k+1][n] with k=ci0, n=co; b1 (k+8) duplicates b0.
        unsigned short h0 = __half_as_ushort(__float2half(w[(ci0 * 16 + co) * 27 + tap]));
        unsigned short h1 = __half_as_ushort(__float2half(w[((ci0 + 1) * 16 + co) * 27 + tap]));
        g_wfrag[idx] = (uint32_t)h0 | ((uint32_t)h1 << 16);
    }
}

// ---------- stage one input d-slice window: per position 8 hi-halves + 8 lo-halves ----------
__device__ __forceinline__ void stage_slice(const float* __restrict__ x, int n, int d, int f0,
                                            uint4* __restrict__ dst, int tid) {
    for (int i = tid; i < 266; i += 256) {
        int q = f0 - 138 + i;
        float v[8];
        #pragma unroll
        for (int ci = 0; ci < 8; ++ci) v[ci] = 0.f;
        if (q >= 0) {
            int qh = q / PLW, qw = q - qh * PLW;
            if (qh < 64 && qw < 64) {
                const float* xp = x + (size_t)n * 8 * SP_I + (size_t)d * 4096 + qh * 64 + qw;
                #pragma unroll
                for (int ci = 0; ci < 8; ++ci) v[ci] = xp[(size_t)ci * SP_I];
            }
        }
        uint32_t hi[4], lo[4];
        #pragma unroll
        for (int j = 0; j < 4; ++j) {
            float a = v[2 * j], b = v[2 * j + 1];
            hi[j] = packh2(a, b);
            float ha = __half2float(__float2half_rn(a));
            float hb = __half2float(__float2half_rn(b));
            lo[j] = packh2(a - ha, b - hb);
        }
        dst[2 * i]     = make_uint4(hi[0], hi[1], hi[2], hi[3]);
        dst[2 * i + 1] = make_uint4(lo[0], lo[1], lo[2], lo[3]);
    }
}

// ---------- conv: HMMA implicit GEMM, output-slice-rotating register accumulators ----------
__global__ __launch_bounds__(256, 2) void conv_kernel(const float* __restrict__ x,
                                                      float* __restrict__ out)
{
    __shared__ uint32_t sWf[1728];
    __shared__ __align__(16) uint4 sX[2][532];    // [buf][pos*2] : 16 hi + 16 lo bytes
    __shared__ float wred[64];

    const int tid = threadIdx.x, warp = tid >> 5, lid = tid & 31;
    const int n = blockIdx.y, f0 = blockIdx.x * 128;

    for (int i = tid; i < 1728; i += 256) sWf[i] = g_wfrag[i];
    stage_slice(x, n, 0, f0, sX[0], tid);

    // ldmatrix lane geometry: tiles (rows0-7,k0-7)(rows8-15,k0-7)(rows0-7,k8-15)(rows8-15,k8-15)
    const uint32_t laneoff = (uint32_t)(((lid & 7) + ((lid >> 3) & 1) * 8) * 32 + ((lid >> 4) & 1) * 16);
    const uint32_t bufb[2] = { smem_u32(sX[0]), smem_u32(sX[1]) };

    // per-lane store geometry (C frag: c0,c1 -> row; c2,c3 -> row+8; cols 2m,2m+1)
    const int posA = f0 + warp * 16 + (lid >> 2);
    const int posB = posA + 8;
    const int ohA = posA / PLW, owA = posA - ohA * PLW;
    const int ohB = posB / PLW, owB = posB - ohB * PLW;
    const bool mA = (posA < PL) && (owA < 66);
    const bool mB = (posB < PL) && (owB < 66);
    float* const outA = out + (size_t)n * 16 * SP_O + ohA * 66 + owA;
    float* const outB = out + (size_t)n * 16 * SP_O + ohB * 66 + owB;
    const int coL = (lid & 3) * 2;
    const int gl  = coL >> 2;             // 0 or 1: group low-bit for this lane

    float acc[3][2][4];                   // [jd -> od=d+jd][nh][frag]
    #pragma unroll
    for (int a = 0; a < 3; ++a)
        #pragma unroll
        for (int h = 0; h < 2; ++h)
            #pragma unroll
            for (int r = 0; r < 4; ++r) acc[a][h][r] = 0.f;

    float s4[4] = {0.f, 0.f, 0.f, 0.f};
    float q4[4] = {0.f, 0.f, 0.f, 0.f};
    __syncthreads();

    #pragma unroll 1
    for (int d = 0; d < 64; ++d) {
        if (d < 63) stage_slice(x, n, d + 1, f0, sX[(d + 1) & 1], tid);

        const uint32_t bb = bufb[d & 1];
        #pragma unroll
        for (int s = 0; s < 9; ++s) {
            const int jh = s / 3, jw = s - jh * 3;
            uint32_t a0, a1, a2, a3;
            ldsm4(a0, a1, a2, a3, bb + (uint32_t)((warp * 16 + 138 - jh * PLW - jw) * 32) + laneoff);
            #pragma unroll
            for (int jd = 0; jd < 3; ++jd) {
                const int tap = jd * 9 + s;
                #pragma unroll
                for (int nh = 0; nh < 2; ++nh) {
                    uint32_t b = sWf[tap * 64 + nh * 32 + lid];
                    mma16816(acc[jd][nh], a0, a1, a2, a3, b);
                }
            }
        }

        // od = d complete -> epilogue from acc[0]
        {
            const size_t off = (size_t)d * 4356;
            #pragma unroll
            for (int nh = 0; nh < 2; ++nh) {
                const int co0 = nh * 8 + coL;
                float v0 = fmaxf(acc[0][nh][0], 0.f), v1 = fmaxf(acc[0][nh][1], 0.f);
                float v2 = fmaxf(acc[0][nh][2], 0.f), v3 = fmaxf(acc[0][nh][3], 0.f);
                float sv = 0.f, sq = 0.f;
                if (mA) {
                    outA[off + (size_t)co0 * SP_O] = v0;
                    outA[off + (size_t)(co0 + 1) * SP_O] = v1;
                    sv += v0 + v1; sq += v0 * v0 + v1 * v1;
                }
                if (mB) {
                    outB[off + (size_t)co0 * SP_O] = v2;
                    outB[off + (size_t)(co0 + 1) * SP_O] = v3;
                    sv += v2 + v3; sq += v2 * v2 + v3 * v3;
                }
                if (gl) { s4[nh * 2 + 1] += sv; q4[nh * 2 + 1] += sq; }
                else    { s4[nh * 2]     += sv; q4[nh * 2]     += sq; }
            }
        }
        // rotate accumulators: od=d+1 -> slot0, od=d+2 -> slot1, fresh slot2
        #pragma unroll
        for (int nh = 0; nh < 2; ++nh)
            #pragma unroll
            for (int r = 0; r < 4; ++r) {
                acc[0][nh][r] = acc[1][nh][r];
                acc[1][nh][r] = acc[2][nh][r];
                acc[2][nh][r] = 0.f;
            }
        __syncthreads();
    }

    // od = 64 (acc[0]) and od = 65 (acc[1])
    #pragma unroll
    for (int e = 0; e < 2; ++e) {
        const size_t off = (size_t)(64 + e) * 4356;
        #pragma unroll
        for (int nh = 0; nh < 2; ++nh) {
            const int co0 = nh * 8 + coL;
            float v0 = fmaxf(acc[e][nh][0], 0.f), v1 = fmaxf(acc[e][nh][1], 0.f);
            float v2 = fmaxf(acc[e][nh][2], 0.f), v3 = fmaxf(acc[e][nh][3], 0.f);
            float sv = 0.f, sq = 0.f;
            if (mA) {
                outA[off + (size_t)co0 * SP_O] = v0;
                outA[off + (size_t)(co0 + 1) * SP_O] = v1;
                sv += v0 + v1; sq += v0 * v0 + v1 * v1;
            }
            if (mB) {
                outB[off + (size_t)co0 * SP_O] = v2;
                outB[off + (size_t)(co0 + 1) * SP_O] = v3;
                sv += v2 + v3; sq += v2 * v2 + v3 * v3;
            }
            if (gl) { s4[nh * 2 + 1] += sv; q4[nh * 2 + 1] += sq; }
            else    { s4[nh * 2]     += sv; q4[nh * 2]     += sq; }
        }
    }

    // block reduction of group stats -> atomics
    #pragma unroll
    for (int g = 0; g < 4; ++g) {
        #pragma unroll
        for (int o = 16; o > 0; o >>= 1) {
            s4[g] += __shfl_down_sync(0xffffffffu, s4[g], o);
            q4[g] += __shfl_down_sync(0xffffffffu, q4[g], o);
        }
    }
    if (lid == 0) {
        #pragma unroll
        for (int g = 0; g < 4; ++g) {
            wred[warp * 8 + g]     = s4[g];
            wred[warp * 8 + 4 + g] = q4[g];
        }
    }
    __syncthreads();
    if (tid < 8) {
        float a = 0.f;
        #pragma unroll
        for (int wI = 0; wI < 8; ++wI) a += wred[wI * 8 + tid];
        if (tid < 4) atomicAdd(&g_sum[n * 4 + tid], a);
        else         atomicAdd(&g_ssum[n * 4 + (tid - 4)], a);
    }
}

__global__ void finalize_stats() {
    int t = threadIdx.x;  // n*4+g
    const float inv_cnt = 1.0f / (4.0f * (float)SP_O);
    float m = g_sum[t] * inv_cnt;
    float v = g_ssum[t] * inv_cnt - m * m;
    g_mean[t] = m;
    g_rstd[t] = rsqrtf(v + 1e-5f);
}

__global__ __launch_bounds__(256) void norm_kernel(float* __restrict__ out,
                                                   const float* __restrict__ gamma,
                                                   const float* __restrict__ beta)
{
    int idx = blockIdx.x * 256 + threadIdx.x;   // float4 index
    int e = idx * 4;
    int c_all = e / SP_O;          // n*16 + c
    int n = c_all >> 4;
    int c = c_all & 15;
    int g = c >> 2;
    float m = g_mean[n * 4 + g];
    float r = g_rstd[n * 4 + g];
    float a = r * gamma[c];
    float b = beta[c] - m * a;
    float4 v = ((const float4*)out)[idx];
    v.x = v.x * a + b;
    v.y = v.y * a + b;
    v.z = v.z * a + b;
    v.w = v.w * a + b;
    ((float4*)out)[idx] = v;
}

extern "C" void kernel_launch(void* const* d_in, const int* in_sizes, int n_in,
                              void* d_out, int out_size) {
    const float* x     = (const float*)d_in[0];
    const float* w     = (const float*)d_in[1];
    const float* gamma = (const float*)d_in[2];
    const float* beta  = (const float*)d_in[3];
    float* out = (float*)d_out;

    prep_weights<<<7, 256>>>(w);
    dim3 grid(36, 8);                    // M-tiles (128 positions), batch
    conv_kernel<<<grid, 256>>>(x, out);
    finalize_stats<<<1, 32>>>();
    norm_kernel<<<35937, 256>>>(out, gamma, beta);
}